// round 16
// baseline (speedup 1.0000x reference)
#include <cuda_runtime.h>
#include <math.h>

#define SLEN 256
#define BATCH 16384
#define PI_F 3.14159265358979323846f
#define R2_F 0.70710678118654752440f

typedef unsigned long long ull;

// ---------- packed f32x2 primitives ----------
__device__ __forceinline__ ull F2MUL(ull a, ull b) {
    ull d; asm("mul.rn.f32x2 %0,%1,%2;" : "=l"(d) : "l"(a), "l"(b)); return d;
}
__device__ __forceinline__ ull F2FMA(ull a, ull b, ull c) {
    ull d; asm("fma.rn.f32x2 %0,%1,%2,%3;" : "=l"(d) : "l"(a), "l"(b), "l"(c)); return d;
}
__device__ __forceinline__ ull F2SUB(ull a, ull b) {
    ull d; asm("sub.rn.f32x2 %0,%1,%2;" : "=l"(d) : "l"(a), "l"(b)); return d;
}
__device__ __forceinline__ ull PACK2(float lo, float hi) {
    ull d; asm("mov.b64 %0,{%1,%2};" : "=l"(d) : "f"(lo), "f"(hi)); return d;
}
__device__ __forceinline__ float2 UNPK(ull v) {
    float2 r; asm("mov.b64 {%0,%1},%2;" : "=f"(r.x), "=f"(r.y) : "l"(v)); return r;
}
__device__ __forceinline__ ull SWAPH(ull v) {
    float2 r = UNPK(v); return PACK2(r.y, r.x);
}
__device__ __forceinline__ ull MIXLH(ull a, ull b) {   // (a.lo, b.hi)
    float2 x = UNPK(a), y = UNPK(b); return PACK2(x.x, y.y);
}
__device__ __forceinline__ ull SHX64(ull v, int m) {
    return __shfl_xor_sync(0xFFFFFFFFu, v, m);
}
__device__ __forceinline__ ull SHI64(ull v, int src) {
    return __shfl_sync(0xFFFFFFFFu, v, src);
}

// ---------- precomputed constants ----------
// d1: [sub][C0,C1|S0,S1|nS0,nS1] as float2 pairs: 4 subs x 6 ull
__device__ float2 g_d1[24];
// d2m: same layout, PREMIXED: hi lane from sub^2 (q0-flipped)
__device__ float2 g_d2m[24];
// phase offsets: [diag 0/1][slot s=q0*8+q1*4+q2*2+q3] (= [d][sub*4 + q2*2+q3])
__device__ float g_off[32];
// RY coefs: [layer m=0(1a),1(1b),2(2b),3(l2a ZYZ)][q][c,s]
__device__ float g_ryf[32];
// KAN scratch rows (x0.5 folded)
__device__ float g_kan[140];
// banked packed KAN: [sub][17] (sub i -> rows (2i, 2i+1); sub 3 -> (6,6))
__device__ float2 g_kanb[68];

__global__ void setup_kernel(const float* __restrict__ p1, const float* __restrict__ p2,
                             const float* __restrict__ base_w, const float* __restrict__ spline_w) {
    __shared__ float sA[4], sC[4];
    int t = threadIdx.x;

    // ---- threads 0-3: per-qubit ZYZ of l2a = H * Rot(a=0,l=1); RY coefs ----
    if (t < 4) {
        int q = t;
        {
            float phi = p1[12 + q * 3 + 0];
            float th  = p1[12 + q * 3 + 1];
            float om  = p1[12 + q * 3 + 2];
            float st, ct; sincosf(0.5f * th, &st, &ct);
            float sp, cp; sincosf(0.5f * (phi + om), &sp, &cp);
            float sm, cm; sincosf(0.5f * (phi - om), &sm, &cm);
            double ar =  (double)cp * ct, ai = -(double)sp * ct;
            double br = -(double)cm * st, bi = -(double)sm * st;
            double dr =  (double)cm * st, di = -(double)sm * st;
            double er =  (double)cp * ct, ei =  (double)sp * ct;
            const double r2 = 0.70710678118654752440;
            double u00r = (ar + dr) * r2, u00i = (ai + di) * r2;
            double u01r = (br + er) * r2, u01i = (bi + ei) * r2;
            double u10r = (ar - dr) * r2, u10i = (ai - di) * r2;
            double u11r = (br - er) * r2, u11i = (bi - ei) * r2;
            double detr = u00r * u11r - u00i * u11i - (u01r * u10r - u01i * u10i);
            double deti = u00r * u11i + u00i * u11r - (u01r * u10i + u01i * u10r);
            double alpha = 0.5 * atan2(deti, detr);
            double ca = cos(-alpha), sa = sin(-alpha);
            double v00r = u00r * ca - u00i * sa, v00i = u00r * sa + u00i * ca;
            double v10r = u10r * ca - u10i * sa, v10i = u10r * sa + u10i * ca;
            double cB = sqrt(v00r * v00r + v00i * v00i);
            double sB = sqrt(v10r * v10r + v10i * v10i);
            double a00 = (cB > 1e-12) ? atan2(v00i, v00r) : 0.0;
            double a10 = (sB > 1e-12) ? atan2(v10i, v10r) : 0.0;
            double ApC = -2.0 * a00;
            double AmC =  2.0 * a10;
            sA[q] = (float)(0.5 * (ApC + AmC));
            sC[q] = (float)(0.5 * (ApC - AmC));
            g_ryf[24 + q * 2 + 0] = (float)cB;
            g_ryf[24 + q * 2 + 1] = (float)sB;
        }
        for (int m = 0; m < 3; m++) {
            int a = (m == 0) ? 0 : 1;
            int l = (m == 2) ? 1 : 0;
            const float* pp = a ? p2 : p1;
            float th = pp[l * 12 + q * 3 + 1];
            g_ryf[m * 8 + q * 2 + 0] = cosf(0.5f * th);
            g_ryf[m * 8 + q * 2 + 1] = sinf(0.5f * th);
        }
    }
    __syncthreads();

    // ---- threads 0-15: one phase slot each for g_off, g_d1, g_d2m ----
    if (t < 16) {
        int s = t;
        int b0 = (s >> 3) & 1, b1 = (s >> 2) & 1, b2 = (s >> 1) & 1, b3 = s & 1;
        float h0 = b0 ? 0.5f : -0.5f, h1 = b1 ? 0.5f : -0.5f;
        float h2 = b2 ? 0.5f : -0.5f, h3 = b3 ? 0.5f : -0.5f;
        int sub = b0 * 2 + b1;

        g_off[s] = h0 * p1[0] + h1 * p1[3] + h2 * p1[6] + h3 * p1[9];

        {
            float v = h0 * p2[0] + h1 * p2[3] + h2 * p2[6] + h3 * p2[9];
            int r0 = b1 ^ b2 ^ b3;
            int r1 = b0 ^ b1 ^ b2 ^ b3;
            int r2 = b0 ^ b2 ^ b3;
            int r3 = b0 ^ b3;
            v += (r0 ? 0.5f : -0.5f) * sA[0] + (r1 ? 0.5f : -0.5f) * sA[1]
               + (r2 ? 0.5f : -0.5f) * sA[2] + (r3 ? 0.5f : -0.5f) * sA[3];
            g_off[16 + s] = v;
        }

        // d1: Domega(1a) + phC at Mn(s) [ring_normal forward map]; bank by sub
        {
            float ph = h0 * p1[2] + h1 * p1[5] + h2 * p1[8] + h3 * p1[11];
            int m1 = b1 ^ b0, m2 = b2 ^ m1, m3 = b3 ^ m2, m0 = b0 ^ m3;
            ph += (m0 ? 0.5f : -0.5f) * sC[0] + (m1 ? 0.5f : -0.5f) * sC[1]
                + (m2 ? 0.5f : -0.5f) * sC[2] + (m3 ? 0.5f : -0.5f) * sC[3];
            float cv, sv; sincosf(ph, &sv, &cv);
            float* f = reinterpret_cast<float*>(g_d1);
            int base = sub * 12 + b2 * 2 + b3;
            f[base] = cv; f[base + 4] = sv; f[base + 8] = -sv;
        }

        // d2m: Dphi(2b)(s) + Domega(1b) at ring-inverse; PREMIX: hi lane -> sub^2
        {
            float ph = h0 * p2[12 + 0] + h1 * p2[12 + 3] + h2 * p2[12 + 6] + h3 * p2[12 + 9];
            int i0 = b0 ^ b3;
            int i1 = b0 ^ b1 ^ b3;
            int i2 = b1 ^ b2;
            int i3 = b2 ^ b3;
            ph += (i0 ? 0.5f : -0.5f) * p2[2] + (i1 ? 0.5f : -0.5f) * p2[5]
                + (i2 ? 0.5f : -0.5f) * p2[8] + (i3 ? 0.5f : -0.5f) * p2[11];
            float cv, sv; sincosf(ph, &sv, &cv);
            int dsub = b3 ? (sub ^ 2) : sub;
            float* f = reinterpret_cast<float*>(g_d2m);
            int base = dsub * 12 + b2 * 2 + b3;
            f[base] = cv; f[base + 4] = sv; f[base + 8] = -sv;
        }
    }

    // ---- threads 16-22: one KAN row each (x0.5 folded into ALL coefs) ----
    if (t >= 16 && t < 23) {
        int o = t - 16;
        const float BP[4][4] = {
            {1.f, -3.f, 3.f, -1.f},
            {23.f, -15.f, -3.f, 3.f},
            {23.f, 15.f, -3.f, -3.f},
            {1.f, 3.f, 3.f, 1.f}
        };
        const float inv48 = 0.5f / 48.0f;
        float c0sum = 0.f;
        for (int in = 0; in < 4; in++) {
            float P[4] = {0.f, 0.f, 0.f, 0.f};
            for (int j = 0; j < 4; j++) {
                float w = spline_w[o * 16 + in * 4 + j] * inv48;
                for (int kk = 0; kk < 4; kk++) P[kk] += w * BP[j][kk];
            }
            g_kan[o * 20 + in]      = 0.5f * base_w[o * 4 + in];
            g_kan[o * 20 + 4 + in]  = P[1];
            g_kan[o * 20 + 8 + in]  = P[2];
            g_kan[o * 20 + 12 + in] = P[3];
            c0sum += P[0];
        }
        g_kan[o * 20 + 16] = c0sum;
    }
    __syncthreads();

    // ---- threads 0-3: banked packed KAN (sub i -> rows 2i, 2i+1; sub3 -> 6,6)
    if (t < 4) {
        int rowA = (t == 3) ? 6 : 2 * t;
        int rowB = (t == 3) ? 6 : 2 * t + 1;
        for (int k = 0; k < 17; k++)
            g_kanb[t * 17 + k] = make_float2(g_kan[rowA * 20 + k],
                                             g_kan[rowB * 20 + k]);
    }
}

// ---------------- 4-way split gates ----------------
// thread bits: p0=q0 (partner ^2), p1=q1 (partner ^1); reg k=q2; lane=q3.
// State R[2], I[2]. "Mixed" rep after skipped C(q3,q0): hi lane from thread^2.

struct RYC {
    ull D0, D1;          // q0 sweep (plain lane-dup or fused lane-mixed)
    ull C1, S1;          // q1 sweep
    ull cc2, ss2, ns2;   // q2 local butterfly
    ull cc3, sm3;        // q3 lane sweep
};

__device__ __forceinline__ void ry4w(ull* R, ull* I, const RYC& c) {
    // q0 (thread ^2)
    {
        ull pr0 = SHX64(R[0], 2), pr1 = SHX64(R[1], 2);
        ull pi0 = SHX64(I[0], 2), pi1 = SHX64(I[1], 2);
        R[0] = F2FMA(c.D1, pr0, F2MUL(c.D0, R[0]));
        R[1] = F2FMA(c.D1, pr1, F2MUL(c.D0, R[1]));
        I[0] = F2FMA(c.D1, pi0, F2MUL(c.D0, I[0]));
        I[1] = F2FMA(c.D1, pi1, F2MUL(c.D0, I[1]));
    }
    // q1 (thread ^1)
    {
        ull pr0 = SHX64(R[0], 1), pr1 = SHX64(R[1], 1);
        ull pi0 = SHX64(I[0], 1), pi1 = SHX64(I[1], 1);
        R[0] = F2FMA(c.S1, pr0, F2MUL(c.C1, R[0]));
        R[1] = F2FMA(c.S1, pr1, F2MUL(c.C1, R[1]));
        I[0] = F2FMA(c.S1, pi0, F2MUL(c.C1, I[0]));
        I[1] = F2FMA(c.S1, pi1, F2MUL(c.C1, I[1]));
    }
    // q2 (local reg butterfly)
    {
        ull a = R[0], b = R[1];
        R[0] = F2FMA(c.ns2, b, F2MUL(c.cc2, a));
        R[1] = F2FMA(c.ss2, a, F2MUL(c.cc2, b));
        a = I[0]; b = I[1];
        I[0] = F2FMA(c.ns2, b, F2MUL(c.cc2, a));
        I[1] = F2FMA(c.ss2, a, F2MUL(c.cc2, b));
    }
    // q3 (lane axis)
#pragma unroll
    for (int k = 0; k < 2; k++) {
        ull v = R[k]; R[k] = F2FMA(c.sm3, SWAPH(v), F2MUL(c.cc3, v));
        ull w = I[k]; I[k] = F2FMA(c.sm3, SWAPH(w), F2MUL(c.cc3, w));
    }
}

__device__ __forceinline__ void diag2(ull* R, ull* I, const ull* d) {
#pragma unroll
    for (int k = 0; k < 2; k++) {
        ull C = d[k], S = d[2 + k], nS = d[4 + k];
        ull r = R[k], im = I[k];
        R[k] = F2FMA(nS, im, F2MUL(C, r));
        I[k] = F2FMA(S, r, F2MUL(C, im));
    }
}

// normal ring without final C(q3,q0)  [round-5 verified mapping]
__device__ __forceinline__ void ring_nox4(ull* R, ull* I, int p0, int p1, int lane) {
    int src = lane ^ p0;                       // C(q0,q1)
    R[0] = SHI64(R[0], src); R[1] = SHI64(R[1], src);
    I[0] = SHI64(I[0], src); I[1] = SHI64(I[1], src);
    {                                          // C(q1,q2)
        ull r0 = R[0], r1 = R[1];
        R[0] = p1 ? r1 : r0; R[1] = p1 ? r0 : r1;
        ull i0 = I[0], i1 = I[1];
        I[0] = p1 ? i1 : i0; I[1] = p1 ? i0 : i1;
    }
    R[1] = SWAPH(R[1]); I[1] = SWAPH(I[1]);    // C(q2,q3)
    // C(q3,q0): SKIPPED -> mixed rep (hi lane from thread^2)
}

// reversed ring: C(1,0) C(2,1) C(3,2) C(0,3)  [round-5 verified mapping]
__device__ __forceinline__ void ring_rev4(ull* R, ull* I, int p0, int p1, int lane) {
    int src = lane ^ (p1 << 1);                // C(q1,q0)
    R[0] = SHI64(R[0], src); R[1] = SHI64(R[1], src);
    I[0] = SHI64(I[0], src); I[1] = SHI64(I[1], src);
    R[1] = SHX64(R[1], 1); I[1] = SHX64(I[1], 1);   // C(q2,q1)
    {                                          // C(q3,q2)
        ull a = R[0], b = R[1]; R[0] = MIXLH(a, b); R[1] = MIXLH(b, a);
        ull c = I[0], d = I[1]; I[0] = MIXLH(c, d); I[1] = MIXLH(d, c);
    }
    if (p0) {                                  // C(q0,q3)
        R[0] = SWAPH(R[0]); R[1] = SWAPH(R[1]);
        I[0] = SWAPH(I[0]); I[1] = SWAPH(I[1]);
    }
}

// 4 fused feature-map phases (PRE-HALVED angles)
__device__ __forceinline__ void phases4h(const float* a, float sp0, float sp1,
                                         float sp01, float* ph) {
    float u = fmaf(sp0, a[0], fmaf(sp1, a[1], sp01 * a[4]));
    float c0 = fmaf(sp1, a[5], -a[2]);
    float spq = a[3] + a[6];
    float smq = a[3] - a[6];
    float upc = u + c0, umc = u - c0;
    ph[0] = upc - spq;
    ph[1] = upc + spq;
    ph[2] = umc - smq;
    ph[3] = umc + smq;
}

__device__ __forceinline__ void qcell4(const float* h_ang, const float* x_ang,
                                       const ull* d1, const ull* d2,
                                       const float* off1, const float* off2,
                                       const RYC& ry0, const RYC& ry1, const RYC& ry2,
                                       const RYC& ryl,
                                       int p0, int p1, int lane,
                                       float sp0, float sp1, float sp01,
                                       float sg0, float sg1, float* ev) {
    ull R[2], I[2];
    float ph[4];

    // D1 on uniform state
    phases4h(h_ang, sp0, sp1, sp01, ph);
#pragma unroll
    for (int j = 0; j < 4; j++) ph[j] += off1[j];
#pragma unroll
    for (int k = 0; k < 2; k++) {
        float s0, c0, s1, c1;
        __sincosf(ph[2 * k], &s0, &c0);
        __sincosf(ph[2 * k + 1], &s1, &c1);
        R[k] = PACK2(c0, c1); I[k] = PACK2(s0, s1);
    }

    // ansatz 1
    ry4w(R, I, ry0);                 // RY(1a) plain
    diag2(R, I, d1);                 // Domega_1a * RZ(C_l2a)∘ring
    ring_nox4(R, I, p0, p1, lane);   // -> mixed
    ry4w(R, I, ryl);                 // RY(B_l2a), fused q0 restores true
    ring_rev4(R, I, p0, p1, lane);

    // D2
    phases4h(x_ang, sp0, sp1, sp01, ph);
#pragma unroll
    for (int j = 0; j < 4; j++) ph[j] += off2[j];
#pragma unroll
    for (int k = 0; k < 2; k++) {
        float s0, c0, s1, c1;
        __sincosf(ph[2 * k], &s0, &c0);
        __sincosf(ph[2 * k + 1], &s1, &c1);
        ull c = PACK2(c0, c1), s = PACK2(s0, s1);
        ull nr = F2SUB(F2MUL(c, R[k]), F2MUL(s, I[k]));
        I[k] = F2FMA(s, R[k], F2MUL(c, I[k]));
        R[k] = nr;
    }

    // ansatz 2
    ry4w(R, I, ry1);                 // RY(1b) plain
    ring_nox4(R, I, p0, p1, lane);   // -> mixed
    diag2(R, I, d2);                 // PREMIXED diag (stays mixed)
    ry4w(R, I, ry2);                 // fused q0 restores true

    // measurement (ring-folded parities): P0=Z(q1q2q3) P1=Z(q0q1) P2=Z(q0q1q2) P3=Z(all)
    float sv0, dv0, sv1, dv1;
    {
        ull P0 = F2FMA(I[0], I[0], F2MUL(R[0], R[0]));
        ull P1 = F2FMA(I[1], I[1], F2MUL(R[1], R[1]));
        float2 f0 = UNPK(P0), f1 = UNPK(P1);
        sv0 = f0.x + f0.y; dv0 = f0.x - f0.y;
        sv1 = f1.x + f1.y; dv1 = f1.x - f1.y;
    }
    float tq = dv0 - dv1;     // (-1)^{q2+q3}
    float sq = sv0 + sv1;     // 1
    float wq = sv0 - sv1;     // (-1)^{q2}
    float ut = sg1 * (tq - __shfl_xor_sync(0xFFFFFFFFu, tq, 1));
    float us = sg1 * (sq - __shfl_xor_sync(0xFFFFFFFFu, sq, 1));
    float uw = sg1 * (wq - __shfl_xor_sync(0xFFFFFFFFu, wq, 1));
    float uxt = __shfl_xor_sync(0xFFFFFFFFu, ut, 2);
    float uxs = __shfl_xor_sync(0xFFFFFFFFu, us, 2);
    float uxw = __shfl_xor_sync(0xFFFFFFFFu, uw, 2);
    const float sc = 1.0f / 16.0f;
    ev[0] = (ut + uxt) * sc;
    ev[1] = sg0 * (us - uxs) * sc;
    ev[2] = sg0 * (uw - uxw) * sc;
    ev[3] = sg0 * (ut - uxt) * sc;
}

// 4-way cooperative packed KAN: one f2 accumulator per thread; 3xSHFL64 +
// branchless selects reconstruct all 7 PRE-HALVED angles in every thread.
__device__ __forceinline__ void kan_coop4(const float* hid, const ull* W,
                                          int p0, int p1, float* oang) {
    float f[16];
#pragma unroll
    for (int in = 0; in < 4; in++) {
        float x = hid[in];
        float e = __expf(-x);
        f[in] = __fdividef(x, 1.0f + e);
        f[4 + in] = x;
        float x2 = x * x;
        f[8 + in] = x2;
        f[12 + in] = x2 * x;
    }
    ull a = W[16];
#pragma unroll
    for (int i = 0; i < 16; i++) a = F2FMA(W[i], PACK2(f[i], f[i]), a);
    ull b = SHX64(a, 1);
    ull c = SHX64(a, 2);
    ull d = SHX64(b, 2);
    // order accs by owner index: m = p1-level swap, v = p0-level swap
    ull m0 = p1 ? b : a, m1 = p1 ? a : b;
    ull m2 = p1 ? d : c, m3 = p1 ? c : d;
    ull v0 = p0 ? m2 : m0;   // (o0,o1)
    ull v1 = p0 ? m3 : m1;   // (o2,o3)
    ull v2 = p0 ? m0 : m2;   // (o4,o5)
    ull v3 = p0 ? m1 : m3;   // (o6,o6)
    float2 r0 = UNPK(v0), r1 = UNPK(v1), r2 = UNPK(v2), r3 = UNPK(v3);
    oang[0] = r0.x; oang[1] = r0.y;
    oang[2] = r1.x; oang[3] = r1.y;
    oang[4] = r2.x; oang[5] = r2.y;
    oang[6] = r3.x;
}

__global__ void __launch_bounds__(128, 4) qrnn_kernel(
    const float* __restrict__ inputs,      // [B, S, 4]
    const float* __restrict__ initial_t,   // [B, 7]
    const float* __restrict__ cw1,         // [16, 4]
    const float* __restrict__ cb1,         // [16]
    const float* __restrict__ cw2,         // [1, 16]
    const float* __restrict__ cb2,         // [1]
    float* __restrict__ out)               // [B]
{
    __shared__ __align__(16) ull s_d1[24];
    __shared__ __align__(16) ull s_d2[24];
    __shared__ __align__(16) ull s_kanb[68];
    int tid = threadIdx.x;
    {
        const ull* a = reinterpret_cast<const ull*>(g_d1);
        const ull* b = reinterpret_cast<const ull*>(g_d2m);
        const ull* c = reinterpret_cast<const ull*>(g_kanb);
        if (tid < 24) s_d1[tid] = a[tid];
        if (tid >= 32 && tid < 56) s_d2[tid - 32] = b[tid - 32];
        if (tid >= 56 && tid < 124) s_kanb[tid - 56] = c[tid - 56];
    }
    __syncthreads();

    int gtid = blockIdx.x * blockDim.x + tid;
    int e = gtid >> 2;
    int sub = gtid & 3;
    int p0 = (sub >> 1) & 1;
    int p1 = sub & 1;
    int lane = tid & 31;
    float sp0 = p0 ? 1.f : -1.f;
    float sp1 = p1 ? 1.f : -1.f;
    float sp01 = (p0 ^ p1) ? 1.f : -1.f;
    float sg0 = -sp0, sg1 = -sp1;       // (-1)^{p}

    const ull* d1 = s_d1 + sub * 6;
    const ull* d2 = s_d2 + sub * 6;
    const ull* kanW = s_kanb + sub * 17;

    float off1[4], off2[4];
#pragma unroll
    for (int j = 0; j < 4; j++) {
        off1[j] = g_off[sub * 4 + j];
        off2[j] = g_off[16 + sub * 4 + j];
    }

    RYC ry[4];   // 0:1a plain, 1:1b plain, 2:2b fused, 3:l2a fused
#pragma unroll
    for (int m = 0; m < 4; m++) {
        float c0 = g_ryf[m * 8 + 0], s0 = g_ryf[m * 8 + 1];
        float c1 = g_ryf[m * 8 + 2], s1 = g_ryf[m * 8 + 3];
        float c2 = g_ryf[m * 8 + 4], s2 = g_ryf[m * 8 + 5];
        float c3 = g_ryf[m * 8 + 6], s3 = g_ryf[m * 8 + 7];
        float s0p = p0 ? s0 : -s0;
        float s1p = p1 ? s1 : -s1;
        if (m >= 2) {
            ry[m].D0 = PACK2(c0, s0p); ry[m].D1 = PACK2(s0p, c0);
        } else {
            ry[m].D0 = PACK2(c0, c0);  ry[m].D1 = PACK2(s0p, s0p);
        }
        ry[m].C1 = PACK2(c1, c1); ry[m].S1 = PACK2(s1p, s1p);
        ry[m].cc2 = PACK2(c2, c2); ry[m].ss2 = PACK2(s2, s2); ry[m].ns2 = PACK2(-s2, -s2);
        ry[m].cc3 = PACK2(c3, c3); ry[m].sm3 = PACK2(-s3, s3);
    }

    // h_ang holds PRE-HALVED angles throughout
    float h_ang[7];
#pragma unroll
    for (int k = 0; k < 7; k++) h_ang[k] = 0.5f * initial_t[e * 7 + k];

    const float4* inp = reinterpret_cast<const float4*>(inputs) + (size_t)e * SLEN;

    float hid[4];
#pragma unroll 1
    for (int t = 0; t < SLEN; t++) {
        float4 xv = inp[t];
        float x_ang[7];   // pre-halved
        x_ang[0] = 0.5f * xv.x; x_ang[1] = 0.5f * xv.y;
        x_ang[2] = 0.5f * xv.z; x_ang[3] = 0.5f * xv.w;
        float u0 = PI_F - xv.x, u1 = PI_F - xv.y, u2 = PI_F - xv.z, u3 = PI_F - xv.w;
        float hu1 = 0.5f * u1, hu2 = 0.5f * u2;
        x_ang[4] = u0 * hu1;
        x_ang[5] = hu1 * u2;
        x_ang[6] = hu2 * u3;
        if (t > 0) kan_coop4(hid, kanW, p0, p1, h_ang);
        qcell4(h_ang, x_ang, d1, d2, off1, off2,
               ry[0], ry[1], ry[2], ry[3], p0, p1, lane,
               sp0, sp1, sp01, sg0, sg1, hid);
    }

    float o = cb2[0];
#pragma unroll 1
    for (int k = 0; k < 16; k++) {
        float a = cb1[k];
        a = fmaf(cw1[k * 4 + 0], hid[0], a);
        a = fmaf(cw1[k * 4 + 1], hid[1], a);
        a = fmaf(cw1[k * 4 + 2], hid[2], a);
        a = fmaf(cw1[k * 4 + 3], hid[3], a);
        o = fmaf(cw2[k], fmaxf(a, 0.0f), o);
    }
    if (sub == 0) out[e] = o;
}

extern "C" void kernel_launch(void* const* d_in, const int* in_sizes, int n_in,
                              void* d_out, int out_size) {
    const float* inputs    = (const float*)d_in[0];
    const float* initial_t = (const float*)d_in[1];
    const float* p1        = (const float*)d_in[2];
    const float* p2        = (const float*)d_in[3];
    const float* base_w    = (const float*)d_in[4];
    const float* spline_w  = (const float*)d_in[5];
    const float* cw1       = (const float*)d_in[6];
    const float* cb1       = (const float*)d_in[7];
    const float* cw2       = (const float*)d_in[8];
    const float* cb2       = (const float*)d_in[9];

    setup_kernel<<<1, 32>>>(p1, p2, base_w, spline_w);
    qrnn_kernel<<<(BATCH * 4) / 128, 128>>>(inputs, initial_t,
                                            cw1, cb1, cw2, cb2, (float*)d_out);
}

// round 17
// speedup vs baseline: 1.2692x; 1.2692x over previous
#include <cuda_runtime.h>
#include <math.h>

#define SLEN 256
#define BATCH 16384
#define PI_F 3.14159265358979323846f
#define R2_F 0.70710678118654752440f

typedef unsigned long long ull;

// ---------- packed f32x2 primitives ----------
__device__ __forceinline__ ull F2MUL(ull a, ull b) {
    ull d; asm("mul.rn.f32x2 %0,%1,%2;" : "=l"(d) : "l"(a), "l"(b)); return d;
}
__device__ __forceinline__ ull F2FMA(ull a, ull b, ull c) {
    ull d; asm("fma.rn.f32x2 %0,%1,%2,%3;" : "=l"(d) : "l"(a), "l"(b), "l"(c)); return d;
}
__device__ __forceinline__ ull F2SUB(ull a, ull b) {
    ull d; asm("sub.rn.f32x2 %0,%1,%2;" : "=l"(d) : "l"(a), "l"(b)); return d;
}
__device__ __forceinline__ ull PACK2(float lo, float hi) {
    ull d; asm("mov.b64 %0,{%1,%2};" : "=l"(d) : "f"(lo), "f"(hi)); return d;
}
__device__ __forceinline__ float2 UNPK(ull v) {
    float2 r; asm("mov.b64 {%0,%1},%2;" : "=f"(r.x), "=f"(r.y) : "l"(v)); return r;
}
__device__ __forceinline__ ull SWAPH(ull v) {
    float2 r = UNPK(v); return PACK2(r.y, r.x);
}
__device__ __forceinline__ ull MIXLH(ull a, ull b) {   // (a.lo, b.hi)
    float2 x = UNPK(a), y = UNPK(b); return PACK2(x.x, y.y);
}
__device__ __forceinline__ ull SHFL64(ull v) {
    return __shfl_xor_sync(0xFFFFFFFFu, v, 1);
}

// ---------- precomputed constants ----------
__device__ float2 g_d1[24];     // diag (omega_1a * RZ(C_l2a)∘ring): [p][C|S|nS]
__device__ float2 g_d2m[24];    // PREMIXED diag (omega1b∘ring * phi2b)
__device__ float g_off[32];     // phase offsets [diag 0/1][slot]
__device__ float g_ryf[32];     // RY coefs [layer 0..3][q][c,s]
__device__ float g_kan[140];    // scratch rows (x0.5 folded)
__device__ float2 g_kanb[68];   // banked packed KAN: [p][acc0|acc1][17]

__global__ void setup_kernel(const float* __restrict__ p1, const float* __restrict__ p2,
                             const float* __restrict__ base_w, const float* __restrict__ spline_w) {
    __shared__ float sA[4], sC[4];
    int t = threadIdx.x;

    // ---- threads 0-3: per-qubit ZYZ of l2a = H * Rot(a=0,l=1); RY coefs ----
    if (t < 4) {
        int q = t;
        {
            float phi = p1[12 + q * 3 + 0];
            float th  = p1[12 + q * 3 + 1];
            float om  = p1[12 + q * 3 + 2];
            float st, ct; sincosf(0.5f * th, &st, &ct);
            float sp, cp; sincosf(0.5f * (phi + om), &sp, &cp);
            float sm, cm; sincosf(0.5f * (phi - om), &sm, &cm);
            double ar =  (double)cp * ct, ai = -(double)sp * ct;
            double br = -(double)cm * st, bi = -(double)sm * st;
            double dr =  (double)cm * st, di = -(double)sm * st;
            double er =  (double)cp * ct, ei =  (double)sp * ct;
            const double r2 = 0.70710678118654752440;
            double u00r = (ar + dr) * r2, u00i = (ai + di) * r2;
            double u01r = (br + er) * r2, u01i = (bi + ei) * r2;
            double u10r = (ar - dr) * r2, u10i = (ai - di) * r2;
            double u11r = (br - er) * r2, u11i = (bi - ei) * r2;
            double detr = u00r * u11r - u00i * u11i - (u01r * u10r - u01i * u10i);
            double deti = u00r * u11i + u00i * u11r - (u01r * u10i + u01i * u10r);
            double alpha = 0.5 * atan2(deti, detr);
            double ca = cos(-alpha), sa = sin(-alpha);
            double v00r = u00r * ca - u00i * sa, v00i = u00r * sa + u00i * ca;
            double v10r = u10r * ca - u10i * sa, v10i = u10r * sa + u10i * ca;
            double cB = sqrt(v00r * v00r + v00i * v00i);
            double sB = sqrt(v10r * v10r + v10i * v10i);
            double a00 = (cB > 1e-12) ? atan2(v00i, v00r) : 0.0;
            double a10 = (sB > 1e-12) ? atan2(v10i, v10r) : 0.0;
            double ApC = -2.0 * a00;
            double AmC =  2.0 * a10;
            sA[q] = (float)(0.5 * (ApC + AmC));
            sC[q] = (float)(0.5 * (ApC - AmC));
            g_ryf[24 + q * 2 + 0] = (float)cB;
            g_ryf[24 + q * 2 + 1] = (float)sB;
        }
        for (int m = 0; m < 3; m++) {
            int a = (m == 0) ? 0 : 1;
            int l = (m == 2) ? 1 : 0;
            const float* pp = a ? p2 : p1;
            float th = pp[l * 12 + q * 3 + 1];
            g_ryf[m * 8 + q * 2 + 0] = cosf(0.5f * th);
            g_ryf[m * 8 + q * 2 + 1] = sinf(0.5f * th);
        }
    }
    __syncthreads();

    // ---- threads 0-15: one phase slot each for g_off, g_d1, g_d2m ----
    if (t < 16) {
        int s = t;
        int b0 = (s >> 3) & 1, b1 = (s >> 2) & 1, b2 = (s >> 1) & 1, b3 = s & 1;
        float h0 = b0 ? 0.5f : -0.5f, h1 = b1 ? 0.5f : -0.5f;
        float h2 = b2 ? 0.5f : -0.5f, h3 = b3 ? 0.5f : -0.5f;

        g_off[s] = h0 * p1[0] + h1 * p1[3] + h2 * p1[6] + h3 * p1[9];

        {
            float v = h0 * p2[0] + h1 * p2[3] + h2 * p2[6] + h3 * p2[9];
            int r0 = b1 ^ b2 ^ b3;
            int r1 = b0 ^ b1 ^ b2 ^ b3;
            int r2 = b0 ^ b2 ^ b3;
            int r3 = b0 ^ b3;
            v += (r0 ? 0.5f : -0.5f) * sA[0] + (r1 ? 0.5f : -0.5f) * sA[1]
               + (r2 ? 0.5f : -0.5f) * sA[2] + (r3 ? 0.5f : -0.5f) * sA[3];
            g_off[16 + s] = v;
        }

        int p = b0, k = (s >> 1) & 3, lane = b3;

        {
            float ph = h0 * p1[2] + h1 * p1[5] + h2 * p1[8] + h3 * p1[11];
            int m1 = b1 ^ b0, m2 = b2 ^ m1, m3 = b3 ^ m2, m0 = b0 ^ m3;
            ph += (m0 ? 0.5f : -0.5f) * sC[0] + (m1 ? 0.5f : -0.5f) * sC[1]
                + (m2 ? 0.5f : -0.5f) * sC[2] + (m3 ? 0.5f : -0.5f) * sC[3];
            float cv, sv; sincosf(ph, &sv, &cv);
            float* f = reinterpret_cast<float*>(g_d1);
            int base = p * 24 + k * 2 + lane;
            f[base] = cv; f[base + 8] = sv; f[base + 16] = -sv;
        }

        {
            float ph = h0 * p2[12 + 0] + h1 * p2[12 + 3] + h2 * p2[12 + 6] + h3 * p2[12 + 9];
            int i0 = b0 ^ b3;
            int i1 = b0 ^ b1 ^ b3;
            int i2 = b1 ^ b2;
            int i3 = b2 ^ b3;
            ph += (i0 ? 0.5f : -0.5f) * p2[2] + (i1 ? 0.5f : -0.5f) * p2[5]
                + (i2 ? 0.5f : -0.5f) * p2[8] + (i3 ? 0.5f : -0.5f) * p2[11];
            float cv, sv; sincosf(ph, &sv, &cv);
            int pd = lane ? (1 - p) : p;
            float* f = reinterpret_cast<float*>(g_d2m);
            int base = pd * 24 + k * 2 + lane;
            f[base] = cv; f[base + 8] = sv; f[base + 16] = -sv;
        }
    }

    // ---- threads 16-22: one KAN row each (x0.5 folded into ALL coefs) ----
    if (t >= 16 && t < 23) {
        int o = t - 16;
        const float BP[4][4] = {
            {1.f, -3.f, 3.f, -1.f},
            {23.f, -15.f, -3.f, 3.f},
            {23.f, 15.f, -3.f, -3.f},
            {1.f, 3.f, 3.f, 1.f}
        };
        const float inv48 = 0.5f / 48.0f;   // 0.5 phase-fold
        float c0sum = 0.f;
        for (int in = 0; in < 4; in++) {
            float P[4] = {0.f, 0.f, 0.f, 0.f};
            for (int j = 0; j < 4; j++) {
                float w = spline_w[o * 16 + in * 4 + j] * inv48;
                for (int kk = 0; kk < 4; kk++) P[kk] += w * BP[j][kk];
            }
            g_kan[o * 20 + in]      = 0.5f * base_w[o * 4 + in];
            g_kan[o * 20 + 4 + in]  = P[1];
            g_kan[o * 20 + 8 + in]  = P[2];
            g_kan[o * 20 + 12 + in] = P[3];
            c0sum += P[0];
        }
        g_kan[o * 20 + 16] = c0sum;
    }
    __syncthreads();

    // ---- threads 0-3: pack banked KAN.
    // bank p=0: acc0 rows (0,1), acc1 rows (2,3)
    // bank p=1: acc0 rows (4,5), acc1 rows (6,6)
    if (t < 4) {
        int rowA = (t == 0) ? 0 : (t == 1) ? 2 : (t == 2) ? 4 : 6;
        int rowB = (t == 3) ? 6 : rowA + 1;
        for (int k = 0; k < 17; k++)
            g_kanb[t * 17 + k] = make_float2(g_kan[rowA * 20 + k],
                                             g_kan[rowB * 20 + k]);
    }
}

// ---------------- split-state gates (round-15 verified, unchanged) ----------------
// thread bit p = q0; regs k: bit1=q1, bit0=q2; f32x2 lane = q3. State R[4], I[4].

struct RYC {
    ull D0, D1;
    ull cc1, ss1, ns1;
    ull cc2, ss2, ns2;
    ull cc3, sm3;
};

__device__ __forceinline__ void ry4(ull* R, ull* I, const RYC& c) {
    {
        ull PR0 = SHFL64(R[0]), PR1 = SHFL64(R[1]), PR2 = SHFL64(R[2]), PR3 = SHFL64(R[3]);
        ull PI0 = SHFL64(I[0]), PI1 = SHFL64(I[1]), PI2 = SHFL64(I[2]), PI3 = SHFL64(I[3]);
        R[0] = F2FMA(c.D1, PR0, F2MUL(c.D0, R[0]));
        R[1] = F2FMA(c.D1, PR1, F2MUL(c.D0, R[1]));
        R[2] = F2FMA(c.D1, PR2, F2MUL(c.D0, R[2]));
        R[3] = F2FMA(c.D1, PR3, F2MUL(c.D0, R[3]));
        I[0] = F2FMA(c.D1, PI0, F2MUL(c.D0, I[0]));
        I[1] = F2FMA(c.D1, PI1, F2MUL(c.D0, I[1]));
        I[2] = F2FMA(c.D1, PI2, F2MUL(c.D0, I[2]));
        I[3] = F2FMA(c.D1, PI3, F2MUL(c.D0, I[3]));
    }
    {
        ull a, b;
        a = R[0]; b = R[2]; R[0] = F2FMA(c.ns1, b, F2MUL(c.cc1, a)); R[2] = F2FMA(c.ss1, a, F2MUL(c.cc1, b));
        a = R[1]; b = R[3]; R[1] = F2FMA(c.ns1, b, F2MUL(c.cc1, a)); R[3] = F2FMA(c.ss1, a, F2MUL(c.cc1, b));
        a = I[0]; b = I[2]; I[0] = F2FMA(c.ns1, b, F2MUL(c.cc1, a)); I[2] = F2FMA(c.ss1, a, F2MUL(c.cc1, b));
        a = I[1]; b = I[3]; I[1] = F2FMA(c.ns1, b, F2MUL(c.cc1, a)); I[3] = F2FMA(c.ss1, a, F2MUL(c.cc1, b));
    }
    {
        ull a, b;
        a = R[0]; b = R[1]; R[0] = F2FMA(c.ns2, b, F2MUL(c.cc2, a)); R[1] = F2FMA(c.ss2, a, F2MUL(c.cc2, b));
        a = R[2]; b = R[3]; R[2] = F2FMA(c.ns2, b, F2MUL(c.cc2, a)); R[3] = F2FMA(c.ss2, a, F2MUL(c.cc2, b));
        a = I[0]; b = I[1]; I[0] = F2FMA(c.ns2, b, F2MUL(c.cc2, a)); I[1] = F2FMA(c.ss2, a, F2MUL(c.cc2, b));
        a = I[2]; b = I[3]; I[2] = F2FMA(c.ns2, b, F2MUL(c.cc2, a)); I[3] = F2FMA(c.ss2, a, F2MUL(c.cc2, b));
    }
#pragma unroll
    for (int k = 0; k < 4; k++) {
        ull v = R[k]; R[k] = F2FMA(c.sm3, SWAPH(v), F2MUL(c.cc3, v));
        ull w = I[k]; I[k] = F2FMA(c.sm3, SWAPH(w), F2MUL(c.cc3, w));
    }
}

__device__ __forceinline__ void diag_apply(ull* R, ull* I, const ull* d) {
#pragma unroll
    for (int k = 0; k < 4; k++) {
        ull C = d[k], S = d[4 + k], nS = d[8 + k];
        ull r = R[k], im = I[k];
        R[k] = F2FMA(nS, im, F2MUL(C, r));
        I[k] = F2FMA(S, r, F2MUL(C, im));
    }
}

__device__ __forceinline__ void ring_normal_nox(ull* R, ull* I, int p) {
    {
        ull r0 = R[0], r1 = R[1], r2 = R[2], r3 = R[3];
        R[0] = p ? r2 : r0; R[2] = p ? r0 : r2;
        R[1] = p ? r3 : r1; R[3] = p ? r1 : r3;
        ull i0 = I[0], i1 = I[1], i2 = I[2], i3 = I[3];
        I[0] = p ? i2 : i0; I[2] = p ? i0 : i2;
        I[1] = p ? i3 : i1; I[3] = p ? i1 : i3;
    }
    { ull t = R[2]; R[2] = R[3]; R[3] = t; t = I[2]; I[2] = I[3]; I[3] = t; }
    R[1] = SWAPH(R[1]); R[3] = SWAPH(R[3]);
    I[1] = SWAPH(I[1]); I[3] = SWAPH(I[3]);
}

__device__ __forceinline__ void ring_rev(ull* R, ull* I, int p) {
    R[2] = SHFL64(R[2]); R[3] = SHFL64(R[3]);
    I[2] = SHFL64(I[2]); I[3] = SHFL64(I[3]);
    { ull t = R[1]; R[1] = R[3]; R[3] = t; t = I[1]; I[1] = I[3]; I[3] = t; }
    {
        ull a = R[0], b = R[1]; R[0] = MIXLH(a, b); R[1] = MIXLH(b, a);
        ull c = R[2], d = R[3]; R[2] = MIXLH(c, d); R[3] = MIXLH(d, c);
        ull e = I[0], f = I[1]; I[0] = MIXLH(e, f); I[1] = MIXLH(f, e);
        ull g = I[2], h = I[3]; I[2] = MIXLH(g, h); I[3] = MIXLH(h, g);
    }
#pragma unroll
    for (int k = 0; k < 4; k++) {
        R[k] = p ? SWAPH(R[k]) : R[k];
        I[k] = p ? SWAPH(I[k]) : I[k];
    }
}

// fused feature-map phases; ang is PRE-HALVED
__device__ __forceinline__ void phases8h(const float* ang, int p, float* ph) {
    float b0 = ang[0], b1 = ang[1], b2 = ang[2], b3 = ang[3];
    float b4 = ang[4], b5 = ang[5], b6 = ang[6];
    float t01 = b0 + b1, d01 = b0 - b1;
    float uA = p ? (d01 + b4) : (-t01 - b4);
    float uB = p ? (t01 - b4) : (-d01 + b4);
    float t23 = b2 + b3, d23 = b2 - b3;
    float e00 = -t23 - b6, e01 = -d23 + b6, e10 = d23 + b6, e11 = t23 - b6;
    ph[0] = uA + (e00 - b5); ph[1] = uA + (e01 - b5);
    ph[2] = uA + (e10 + b5); ph[3] = uA + (e11 + b5);
    ph[4] = uB + (e00 + b5); ph[5] = uB + (e01 + b5);
    ph[6] = uB + (e10 - b5); ph[7] = uB + (e11 - b5);
}

__device__ __forceinline__ void qcell(const float* h_ang, const float* x_ang,
                                      const ull* d1, const ull* d2,
                                      const float* off1, const float* off2,
                                      const RYC& ry0, const RYC& ry1, const RYC& ry2,
                                      const RYC& ryl,
                                      int p, float sgnp, float* ev) {
    ull R[4], I[4];
    float ph[8];

    phases8h(h_ang, p, ph);
#pragma unroll
    for (int s = 0; s < 8; s++) ph[s] += off1[s];
#pragma unroll
    for (int k = 0; k < 4; k++) {
        float s0, c0, s1, c1;
        __sincosf(ph[2 * k], &s0, &c0);
        __sincosf(ph[2 * k + 1], &s1, &c1);
        R[k] = PACK2(c0, c1); I[k] = PACK2(s0, s1);
    }

    // ansatz 1
    ry4(R, I, ry0);
    diag_apply(R, I, d1);
    ring_normal_nox(R, I, p);
    ry4(R, I, ryl);
    ring_rev(R, I, p);

    // D2
    phases8h(x_ang, p, ph);
#pragma unroll
    for (int s = 0; s < 8; s++) ph[s] += off2[s];
#pragma unroll
    for (int k = 0; k < 4; k++) {
        float s0, c0, s1, c1;
        __sincosf(ph[2 * k], &s0, &c0);
        __sincosf(ph[2 * k + 1], &s1, &c1);
        ull c = PACK2(c0, c1), s = PACK2(s0, s1);
        ull nr = F2SUB(F2MUL(c, R[k]), F2MUL(s, I[k]));
        I[k] = F2FMA(s, R[k], F2MUL(c, I[k]));
        R[k] = nr;
    }

    // ansatz 2
    ry4(R, I, ry1);
    ring_normal_nox(R, I, p);
    diag_apply(R, I, d2);
    ry4(R, I, ry2);

    // measurement
    float sv[4], dv[4];
#pragma unroll
    for (int k = 0; k < 4; k++) {
        ull P = F2FMA(I[k], I[k], F2MUL(R[k], R[k]));
        float2 f = UNPK(P);
        sv[k] = f.x + f.y;
        dv[k] = f.x - f.y;
    }
    float A = dv[0] - dv[1] - dv[2] + dv[3];
    float C = sv[0] + sv[1] - sv[2] - sv[3];
    float D = sv[0] - sv[1] - sv[2] + sv[3];
    float Ax = __shfl_xor_sync(0xFFFFFFFFu, A, 1);
    float Cx = __shfl_xor_sync(0xFFFFFFFFu, C, 1);
    float Dx = __shfl_xor_sync(0xFFFFFFFFu, D, 1);
    const float sc = 1.0f / 16.0f;
    ev[0] = (A + Ax) * sc;
    ev[1] = sgnp * (C - Cx) * sc;
    ev[2] = sgnp * (D - Dx) * sc;
    ev[3] = sgnp * (A - Ax) * sc;
}

// Cooperative PACKED KAN [round-15 verified]
__device__ __forceinline__ void kan_coop(const float* hid, const ull* W, int p,
                                         float* oang) {
    float f[16];
#pragma unroll
    for (int in = 0; in < 4; in++) {
        float x = hid[in];
        float e = __expf(-x);
        f[in] = __fdividef(x, 1.0f + e);     // silu
        f[4 + in] = x;
        float x2 = x * x;
        f[8 + in] = x2;
        f[12 + in] = x2 * x;
    }
    ull a0 = W[16], a1 = W[17 + 16];
#pragma unroll
    for (int i = 0; i < 16; i++) {
        ull F = PACK2(f[i], f[i]);
        a0 = F2FMA(W[i], F, a0);
        a1 = F2FMA(W[17 + i], F, a1);
    }
    ull b0 = SHFL64(a0), b1 = SHFL64(a1);
    ull u0 = p ? b0 : a0;   // (o0,o1)
    ull u1 = p ? b1 : a1;   // (o2,o3)
    ull u2 = p ? a0 : b0;   // (o4,o5)
    ull u3 = p ? a1 : b1;   // (o6,o6)
    float2 v0 = UNPK(u0), v1 = UNPK(u1), v2 = UNPK(u2), v3 = UNPK(u3);
    oang[0] = v0.x; oang[1] = v0.y;
    oang[2] = v1.x; oang[3] = v1.y;
    oang[4] = v2.x; oang[5] = v2.y;
    oang[6] = v3.x;
}

__device__ __forceinline__ void build_xang(float4 xv, float* x_ang) {
    x_ang[0] = 0.5f * xv.x; x_ang[1] = 0.5f * xv.y;
    x_ang[2] = 0.5f * xv.z; x_ang[3] = 0.5f * xv.w;
    float u0 = PI_F - xv.x, u1 = PI_F - xv.y, u2 = PI_F - xv.z, u3 = PI_F - xv.w;
    float hu1 = 0.5f * u1, hu2 = 0.5f * u2;
    x_ang[4] = u0 * hu1;
    x_ang[5] = hu1 * u2;
    x_ang[6] = hu2 * u3;
}

__global__ void __launch_bounds__(128, 2) qrnn_kernel(
    const float* __restrict__ inputs,      // [B, S, 4]
    const float* __restrict__ initial_t,   // [B, 7]
    const float* __restrict__ cw1,         // [16, 4]
    const float* __restrict__ cb1,         // [16]
    const float* __restrict__ cw2,         // [1, 16]
    const float* __restrict__ cb2,         // [1]
    float* __restrict__ out)               // [B]
{
    __shared__ __align__(16) ull s_kanb[68];
    int tid = threadIdx.x;
    {
        const ull* a = reinterpret_cast<const ull*>(g_kanb);
        if (tid < 68) s_kanb[tid] = a[tid];
    }
    __syncthreads();

    int gtid = blockIdx.x * blockDim.x + tid;
    int e = gtid >> 1;
    int p = gtid & 1;
    float sgnp = p ? -1.0f : 1.0f;
    const ull* kanW = s_kanb + p * 34;

    float off1[8], off2[8];
#pragma unroll
    for (int s = 0; s < 8; s++) {
        off1[s] = g_off[p * 8 + s];
        off2[s] = g_off[16 + p * 8 + s];
    }
    RYC ry[4];   // 0:1a plain, 1:1b plain, 2:2b fused, 3:l2a fused
#pragma unroll
    for (int m = 0; m < 4; m++) {
        float c0 = g_ryf[m * 8 + 0], s0 = g_ryf[m * 8 + 1];
        float c1 = g_ryf[m * 8 + 2], s1 = g_ryf[m * 8 + 3];
        float c2 = g_ryf[m * 8 + 4], s2 = g_ryf[m * 8 + 5];
        float c3 = g_ryf[m * 8 + 6], s3 = g_ryf[m * 8 + 7];
        float s0p = p ? s0 : -s0;
        if (m >= 2) {
            ry[m].D0 = PACK2(c0, s0p); ry[m].D1 = PACK2(s0p, c0);
        } else {
            ry[m].D0 = PACK2(c0, c0);  ry[m].D1 = PACK2(s0p, s0p);
        }
        ry[m].cc1 = PACK2(c1, c1); ry[m].ss1 = PACK2(s1, s1); ry[m].ns1 = PACK2(-s1, -s1);
        ry[m].cc2 = PACK2(c2, c2); ry[m].ss2 = PACK2(s2, s2); ry[m].ns2 = PACK2(-s2, -s2);
        ry[m].cc3 = PACK2(c3, c3); ry[m].sm3 = PACK2(-s3, s3);
    }
    ull d1r[12], d2r[12];
    {
        const ull* b = reinterpret_cast<const ull*>(g_d1) + p * 12;
        const ull* c = reinterpret_cast<const ull*>(g_d2m) + p * 12;
#pragma unroll
        for (int i = 0; i < 12; i++) { d1r[i] = b[i]; d2r[i] = c[i]; }
    }

    // h_ang holds PRE-HALVED angles throughout
    float h_ang[7];
#pragma unroll
    for (int k = 0; k < 7; k++) h_ang[k] = 0.5f * initial_t[e * 7 + k];

    const float4* inp = reinterpret_cast<const float4*>(inputs) + (size_t)e * SLEN;

    float hid[4];
    float x_ang[7];

    // ---- peeled step 0 (no KAN) ----
    float4 xv_next = inp[0];
    build_xang(xv_next, x_ang);
    xv_next = inp[1];                 // prefetch step 1
    qcell(h_ang, x_ang, d1r, d2r, off1, off2,
          ry[0], ry[1], ry[2], ry[3], p, sgnp, hid);

    // ---- steady-state loop: t = 1 .. SLEN-1 ----
#pragma unroll 1
    for (int t = 1; t < SLEN; t++) {
        build_xang(xv_next, x_ang);
        if (t + 1 < SLEN) xv_next = inp[t + 1];   // prefetch next input
        kan_coop(hid, kanW, p, h_ang);
        qcell(h_ang, x_ang, d1r, d2r, off1, off2,
              ry[0], ry[1], ry[2], ry[3], p, sgnp, hid);
    }

    float o = cb2[0];
#pragma unroll 1
    for (int k = 0; k < 16; k++) {
        float a = cb1[k];
        a = fmaf(cw1[k * 4 + 0], hid[0], a);
        a = fmaf(cw1[k * 4 + 1], hid[1], a);
        a = fmaf(cw1[k * 4 + 2], hid[2], a);
        a = fmaf(cw1[k * 4 + 3], hid[3], a);
        o = fmaf(cw2[k], fmaxf(a, 0.0f), o);
    }
    if (p == 0) out[e] = o;
}

extern "C" void kernel_launch(void* const* d_in, const int* in_sizes, int n_in,
                              void* d_out, int out_size) {
    const float* inputs    = (const float*)d_in[0];
    const float* initial_t = (const float*)d_in[1];
    const float* p1        = (const float*)d_in[2];
    const float* p2        = (const float*)d_in[3];
    const float* base_w    = (const float*)d_in[4];
    const float* spline_w  = (const float*)d_in[5];
    const float* cw1       = (const float*)d_in[6];
    const float* cb1       = (const float*)d_in[7];
    const float* cw2       = (const float*)d_in[8];
    const float* cb2       = (const float*)d_in[9];

    setup_kernel<<<1, 32>>>(p1, p2, base_w, spline_w);
    qrnn_kernel<<<(BATCH * 2) / 128, 128>>>(inputs, initial_t,
                                            cw1, cb1, cw2, cb2, (float*)d_out);
}